// round 14
// baseline (speedup 1.0000x reference)
#include <cuda_runtime.h>
#include <float.h>

#define N_NODES 588
#define K_DEG   32

// -------- global scratch (allocation-free: __device__ arrays) --------
__device__ __align__(16) float g_x1[N_NODES * 3];
__device__ __align__(16) float g_act4[512];
__device__ __align__(16) float g_act5[1024];

__device__ __forceinline__ float lrelu(float x) { return x > 0.f ? x : 0.01f * x; }

__device__ __forceinline__ float warp_sum(float v) {
#pragma unroll
    for (int o = 16; o; o >>= 1) v += __shfl_xor_sync(0xffffffffu, v, o);
    return v;
}

// PDL: launch_dependents at kernel END (R7-proven optimal; top-launch R9 and
// post-wait R13 both regressed). wait before consuming predecessor data.
__device__ __forceinline__ void pdl_launch() { asm volatile("griddepcontrol.launch_dependents;" ::: "memory"); }
__device__ __forceinline__ void pdl_wait()   { asm volatile("griddepcontrol.wait;" ::: "memory"); }

// ============ K1: EdgeConv1 — 5 blocks, redundant a1/c1, split gather ============
// Decomposition: msg = a1[src] + c1[dst]; max over src commutes with +c1.
#define EC1_BLKS 5
#define EC1_NPB  118   // 5*118 = 590 >= 588

__global__ void __launch_bounds__(128, 1) k_ec1(
    const float* __restrict__ features, const int* __restrict__ src,
    const float* __restrict__ t1w, const float* __restrict__ t1b,
    const float* __restrict__ p1w, const float* __restrict__ p1b)
{
    const int t = threadIdx.x;
    __shared__ float a1[N_NODES * 3], c1[N_NODES * 3];

    float T1[9], P1[9], B1[3];
#pragma unroll
    for (int i = 0; i < 9; i++) { T1[i] = t1w[i]; P1[i] = p1w[i]; }
#pragma unroll
    for (int i = 0; i < 3; i++) B1[i] = t1b[i] + p1b[i];

    for (int j = t; j < N_NODES; j += 128) {
        float v0 = features[j * 3], v1 = features[j * 3 + 1], v2 = features[j * 3 + 2];
#pragma unroll
        for (int k = 0; k < 3; k++) {
            float av = T1[k * 3] * v0 + T1[k * 3 + 1] * v1 + T1[k * 3 + 2] * v2;
            float pv = P1[k * 3] * v0 + P1[k * 3 + 1] * v1 + P1[k * 3 + 2] * v2;
            a1[j * 3 + k] = av;
            c1[j * 3 + k] = B1[k] + pv - av;
        }
    }
    __syncthreads();

    int i = blockIdx.x * EC1_NPB + t;
    if (t < EC1_NPB && i < N_NODES) {
        float m0 = -FLT_MAX, m1 = -FLT_MAX, m2 = -FLT_MAX;
        const int* sp = src + i * K_DEG;
#pragma unroll
        for (int e = 0; e < K_DEG; e++) {
            int s = sp[e] * 3;
            m0 = fmaxf(m0, a1[s]);
            m1 = fmaxf(m1, a1[s + 1]);
            m2 = fmaxf(m2, a1[s + 2]);
        }
        g_x1[i * 3]     = m0 + c1[i * 3];
        g_x1[i * 3 + 1] = m1 + c1[i * 3 + 1];
        g_x1[i * 3 + 2] = m2 + c1[i * 3 + 2];
    }
    pdl_launch();
}

// == K2: EC2 + fc1 + fc2 (redundant) + fc3 FULL (redundant->shared) + fc4 slice ==
// 32 blocks x 256. Removes the former k_fc4 node (one hop, ~5us) for ~2.5us of
// extra redundant fc3 work per block.
__global__ void __launch_bounds__(256, 1) k_mid(
    const int* __restrict__ src,
    const float* __restrict__ t2w, const float* __restrict__ t2b,
    const float* __restrict__ p2w, const float* __restrict__ p2b,
    const float* __restrict__ fc1w, const float* __restrict__ fc1b,
    const float* __restrict__ fc2w, const float* __restrict__ fc2b,
    const float* __restrict__ fc3w, const float* __restrict__ fc3b,
    const float* __restrict__ fc4w, const float* __restrict__ fc4b)
{
    const int tid  = threadIdx.x;
    const int warp = tid >> 5;
    const int lane = tid & 31;

    __shared__ float a2[N_NODES], c2[N_NODES], x2[N_NODES];
    __shared__ float y10[10];
    __shared__ __align__(16) float y128[128];
    __shared__ __align__(16) float s_act3[256];

    // ---- pre-wait prologue: external-input-only loads ----
    float T2[3], P2[3];
#pragma unroll
    for (int i = 0; i < 3; i++) { T2[i] = t2w[i]; P2[i] = p2w[i]; }
    float B2 = t2b[0] + p2b[0];
    // fc4 slice: rows r0, r0+1 per warp (16 rows/block, 32 blocks -> 512)
    int r0 = blockIdx.x * 16 + warp * 2;
    float4 W4a[2], W4b[2];
    {
        const float4* pa = (const float4*)(fc4w + r0 * 256);
        const float4* pb = (const float4*)(fc4w + (r0 + 1) * 256);
#pragma unroll
        for (int it = 0; it < 2; it++) { W4a[it] = pa[lane + 32 * it]; W4b[it] = pb[lane + 32 * it]; }
    }
    float b4a = fc4b[r0], b4b = fc4b[r0 + 1];

    pdl_wait();   // g_x1 ready

    // ---- EC2 decomposition (redundant) ----
    for (int j = tid; j < N_NODES; j += 256) {
        float v0 = g_x1[j * 3], v1 = g_x1[j * 3 + 1], v2 = g_x1[j * 3 + 2];
        float av = T2[0] * v0 + T2[1] * v1 + T2[2] * v2;
        a2[j] = av;
        c2[j] = B2 + P2[0] * v0 + P2[1] * v1 + P2[2] * v2 - av;
    }
    __syncthreads();

    for (int i = tid; i < N_NODES; i += 256) {
        float m = -FLT_MAX;
        const int* sp = src + i * K_DEG;
#pragma unroll
        for (int e = 0; e < K_DEG; e++) m = fmaxf(m, a2[sp[e]]);
        x2[i] = m + c2[i];
    }
    __syncthreads();

    // ---- fc1: [588]->[10], warp-per-output; 588 = 18*32 + 12 ----
    for (int k = warp; k < 10; k += 8) {
        const float* wrow = fc1w + k * N_NODES;
        float acc = 0.f;
#pragma unroll
        for (int it = 0; it < 18; it++) {
            int j = it * 32 + lane;
            acc += x2[j] * wrow[j];
        }
        if (lane < 12) {
            int j = 18 * 32 + lane;
            acc += x2[j] * wrow[j];
        }
        acc = warp_sum(acc);
        if (lane == 0) y10[k] = lrelu(acc + fc1b[k]);
    }
    __syncthreads();

    // ---- fc2: [10]->[128] ----
    if (tid < 128) {
        float acc = fc2b[tid];
#pragma unroll
        for (int j = 0; j < 10; j++) acc += y10[j] * fc2w[tid * 10 + j];
        y128[tid] = lrelu(acc);
    }
    __syncthreads();

    // ---- fc3 FULL (redundant): 32 rows/warp, 4 passes of 8 rows -> shared ----
    {
        float4 a4 = ((const float4*)y128)[lane];
#pragma unroll
        for (int pass = 0; pass < 4; pass++) {
            int kb = warp * 32 + pass * 8;
            float acc[8];
#pragma unroll
            for (int q = 0; q < 8; q++) {
                float4 w4 = *((const float4*)(fc3w + (kb + q) * 128) + lane);
                acc[q] = w4.x * a4.x + w4.y * a4.y + w4.z * a4.z + w4.w * a4.w;
            }
#pragma unroll
            for (int q = 0; q < 8; q++) acc[q] = warp_sum(acc[q]);
            if (lane == 0) {
#pragma unroll
                for (int q = 0; q < 8; q++)
                    s_act3[kb + q] = lrelu(acc[q] + fc3b[kb + q]);
            }
        }
    }
    __syncthreads();

    // ---- fc4 slice: 2 rows/warp from shared act3 (weights preloaded) ----
    {
        const float4* sa = (const float4*)s_act3;
        float4 A0 = sa[lane], A1 = sa[lane + 32];
        float acc0 = W4a[0].x * A0.x + W4a[0].y * A0.y + W4a[0].z * A0.z + W4a[0].w * A0.w
                   + W4a[1].x * A1.x + W4a[1].y * A1.y + W4a[1].z * A1.z + W4a[1].w * A1.w;
        float acc1 = W4b[0].x * A0.x + W4b[0].y * A0.y + W4b[0].z * A0.z + W4b[0].w * A0.w
                   + W4b[1].x * A1.x + W4b[1].y * A1.y + W4b[1].z * A1.z + W4b[1].w * A1.w;
        acc0 = warp_sum(acc0);
        acc1 = warp_sum(acc1);
        if (lane == 0) {
            g_act4[r0]     = lrelu(acc0 + b4a);
            g_act4[r0 + 1] = lrelu(acc1 + b4b);
        }
    }
    pdl_launch();
}

// ================= K3: fc5 [512]->[1024], warp-per-row =================
__global__ void __launch_bounds__(256, 1) k_fc5(
    const float* __restrict__ w, const float* __restrict__ b)
{
    int gw   = blockIdx.x * 8 + (threadIdx.x >> 5);   // 0..1023
    int lane = threadIdx.x & 31;
    const float4* wr = (const float4*)(w + gw * 512);
    float4 W[4];
#pragma unroll
    for (int it = 0; it < 4; it++) W[it] = wr[lane + 32 * it];
    float bb = b[gw];

    pdl_wait();   // g_act4 ready

    const float4* ar = (const float4*)g_act4;
    float acc = 0.f;
#pragma unroll
    for (int it = 0; it < 4; it++) {
        float4 a4 = ar[lane + 32 * it];
        acc += W[it].x * a4.x + W[it].y * a4.y + W[it].z * a4.z + W[it].w * a4.w;
    }
    acc = warp_sum(acc);
    if (lane == 0) g_act5[gw] = lrelu(acc + bb);
    pdl_launch();
}

// ================= K4: fc6 [1024]->[1764], warp-per-row =================
__global__ void __launch_bounds__(256, 1) k_fc6(
    const float* __restrict__ w, const float* __restrict__ b,
    float* __restrict__ out)
{
    int gw   = blockIdx.x * 8 + (threadIdx.x >> 5);   // 0..1767
    int lane = threadIdx.x & 31;
    bool valid = (gw < 1764);
    int gwc = valid ? gw : 0;

    const float4* wr = (const float4*)(w + (size_t)gwc * 1024);
    float4 W[8];
#pragma unroll
    for (int it = 0; it < 8; it++) W[it] = wr[lane + 32 * it];
    float bb = b[gwc];

    pdl_wait();   // g_act5 ready (uniform across block)

    const float4* ar = (const float4*)g_act5;
    float acc = 0.f;
#pragma unroll
    for (int it = 0; it < 8; it++) {
        float4 a4 = ar[lane + 32 * it];
        acc += W[it].x * a4.x + W[it].y * a4.y + W[it].z * a4.z + W[it].w * a4.w;
    }
    acc = warp_sum(acc);
    if (lane == 0 && valid) out[gw] = acc + bb;
}

// -------- host-side PDL launch helper --------
template <typename... Args>
static void launch_pdl(void (*kern)(Args...), dim3 grid, dim3 blk, Args... args) {
    cudaLaunchConfig_t cfg = {};
    cfg.gridDim = grid;
    cfg.blockDim = blk;
    cfg.dynamicSmemBytes = 0;
    cfg.stream = 0;
    cudaLaunchAttribute attr[1];
    attr[0].id = cudaLaunchAttributeProgrammaticStreamSerialization;
    attr[0].val.programmaticStreamSerializationAllowed = 1;
    cfg.attrs = attr;
    cfg.numAttrs = 1;
    cudaLaunchKernelEx(&cfg, kern, args...);
}

extern "C" void kernel_launch(void* const* d_in, const int* in_sizes, int n_in,
                              void* d_out, int out_size) {
    // metadata order:
    // 0 features, 1 src, 2 dst (unused: dst[e] == e/32 by construction),
    // 3 theta1_w, 4 theta1_b, 5 phi1_w, 6 phi1_b,
    // 7 theta2_w, 8 theta2_b, 9 phi2_w, 10 phi2_b,
    // 11 fc1_w, 12 fc1_b, 13 fc2_w, 14 fc2_b, 15 fc3_w, 16 fc3_b,
    // 17 fc4_w, 18 fc4_b, 19 fc5_w, 20 fc5_b, 21 fc6_w, 22 fc6_b
    launch_pdl(k_ec1, dim3(EC1_BLKS), dim3(128),
        (const float*)d_in[0], (const int*)d_in[1],
        (const float*)d_in[3], (const float*)d_in[4],
        (const float*)d_in[5], (const float*)d_in[6]);
    launch_pdl(k_mid, dim3(32), dim3(256),
        (const int*)d_in[1],
        (const float*)d_in[7], (const float*)d_in[8],
        (const float*)d_in[9], (const float*)d_in[10],
        (const float*)d_in[11], (const float*)d_in[12],
        (const float*)d_in[13], (const float*)d_in[14],
        (const float*)d_in[15], (const float*)d_in[16],
        (const float*)d_in[17], (const float*)d_in[18]);
    launch_pdl(k_fc5, dim3(128), dim3(256),
        (const float*)d_in[19], (const float*)d_in[20]);
    launch_pdl(k_fc6, dim3(221), dim3(256),
        (const float*)d_in[21], (const float*)d_in[22], (float*)d_out);
}

// round 15
// speedup vs baseline: 1.0897x; 1.0897x over previous
#include <cuda_runtime.h>
#include <float.h>

#define N_NODES 588
#define K_DEG   32
#define CLU     8          // cluster size (portable max)
#define EC1_NPB 74         // 8*74 = 592 >= 588

// -------- global scratch (allocation-free: __device__ arrays) --------
__device__ __align__(16) float g_x1[N_NODES * 3];
__device__ __align__(16) float g_act3[256];
__device__ __align__(16) float g_act4[512];
__device__ __align__(16) float g_act5[1024];

__device__ __forceinline__ float lrelu(float x) { return x > 0.f ? x : 0.01f * x; }

__device__ __forceinline__ float warp_sum(float v) {
#pragma unroll
    for (int o = 16; o; o >>= 1) v += __shfl_xor_sync(0xffffffffu, v, o);
    return v;
}

// PDL: end-launch (R7-proven optimal placement).
__device__ __forceinline__ void pdl_launch() { asm volatile("griddepcontrol.launch_dependents;" ::: "memory"); }
__device__ __forceinline__ void pdl_wait()   { asm volatile("griddepcontrol.wait;" ::: "memory"); }

// HW cluster barrier with global-memory release/acquire around it.
// gpu-scope threadfence flushes/invalidates L1D (CCTL.IVALL), so peer-CTA
// global stores are visible after the wait.
__device__ __forceinline__ void cluster_sync_gmem() {
    __threadfence();   // release our global stores
    asm volatile("barrier.cluster.arrive.aligned;" ::: "memory");
    asm volatile("barrier.cluster.wait.aligned;" ::: "memory");
    __threadfence();   // acquire: invalidate stale L1 lines
}

// ====== K1: ONE 8-CTA cluster — EC1 | sync | EC2+fc1+fc2+fc3 | sync | fc4 ======
__global__ void __launch_bounds__(256, 1) k_head(
    const float* __restrict__ features, const int* __restrict__ src,
    const float* __restrict__ t1w, const float* __restrict__ t1b,
    const float* __restrict__ p1w, const float* __restrict__ p1b,
    const float* __restrict__ t2w, const float* __restrict__ t2b,
    const float* __restrict__ p2w, const float* __restrict__ p2b,
    const float* __restrict__ fc1w, const float* __restrict__ fc1b,
    const float* __restrict__ fc2w, const float* __restrict__ fc2b,
    const float* __restrict__ fc3w, const float* __restrict__ fc3b,
    const float* __restrict__ fc4w, const float* __restrict__ fc4b)
{
    const int tid  = threadIdx.x;
    const int bid  = blockIdx.x;           // 0..7 (== cluster rank; 1 cluster)
    const int warp = tid >> 5;
    const int lane = tid & 31;

    __shared__ float a1[N_NODES * 3], c1[N_NODES * 3];
    __shared__ float a2[N_NODES], c2[N_NODES], x2[N_NODES];
    __shared__ float y10[10];
    __shared__ __align__(16) float y128[128];

    // ---------- Phase A: EC1 — redundant a1/c1, split gather ----------
    // msg = a1[src] + c1[dst]; max over src commutes with +c1.
    {
        float T1[9], P1[9], B1[3];
#pragma unroll
        for (int i = 0; i < 9; i++) { T1[i] = t1w[i]; P1[i] = p1w[i]; }
#pragma unroll
        for (int i = 0; i < 3; i++) B1[i] = t1b[i] + p1b[i];

        for (int j = tid; j < N_NODES; j += 256) {
            float v0 = features[j * 3], v1 = features[j * 3 + 1], v2 = features[j * 3 + 2];
#pragma unroll
            for (int k = 0; k < 3; k++) {
                float av = T1[k * 3] * v0 + T1[k * 3 + 1] * v1 + T1[k * 3 + 2] * v2;
                float pv = P1[k * 3] * v0 + P1[k * 3 + 1] * v1 + P1[k * 3 + 2] * v2;
                a1[j * 3 + k] = av;
                c1[j * 3 + k] = B1[k] + pv - av;
            }
        }
        __syncthreads();

        int i = bid * EC1_NPB + tid;
        if (tid < EC1_NPB && i < N_NODES) {
            float m0 = -FLT_MAX, m1 = -FLT_MAX, m2 = -FLT_MAX;
            const int* sp = src + i * K_DEG;
#pragma unroll
            for (int e = 0; e < K_DEG; e++) {
                int s = sp[e] * 3;
                m0 = fmaxf(m0, a1[s]);
                m1 = fmaxf(m1, a1[s + 1]);
                m2 = fmaxf(m2, a1[s + 2]);
            }
            g_x1[i * 3]     = m0 + c1[i * 3];
            g_x1[i * 3 + 1] = m1 + c1[i * 3 + 1];
            g_x1[i * 3 + 2] = m2 + c1[i * 3 + 2];
        }
    }
    cluster_sync_gmem();   // g_x1 complete across cluster

    // ---------- Phase B: EC2 + fc1 + fc2 (redundant) + fc3 split ----------
    {
        float T2[3], P2[3];
#pragma unroll
        for (int i = 0; i < 3; i++) { T2[i] = t2w[i]; P2[i] = p2w[i]; }
        float B2 = t2b[0] + p2b[0];
        for (int j = tid; j < N_NODES; j += 256) {
            float v0 = g_x1[j * 3], v1 = g_x1[j * 3 + 1], v2 = g_x1[j * 3 + 2];
            float av = T2[0] * v0 + T2[1] * v1 + T2[2] * v2;
            a2[j] = av;
            c2[j] = B2 + P2[0] * v0 + P2[1] * v1 + P2[2] * v2 - av;
        }
        __syncthreads();

        for (int i = tid; i < N_NODES; i += 256) {
            float m = -FLT_MAX;
            const int* sp = src + i * K_DEG;
#pragma unroll
            for (int e = 0; e < K_DEG; e++) m = fmaxf(m, a2[sp[e]]);
            x2[i] = m + c2[i];
        }
        __syncthreads();

        // fc1: [588]->[10]; 588 = 18*32 + 12
        for (int k = warp; k < 10; k += 8) {
            const float* wrow = fc1w + k * N_NODES;
            float acc = 0.f;
#pragma unroll
            for (int it = 0; it < 18; it++) {
                int j = it * 32 + lane;
                acc += x2[j] * wrow[j];
            }
            if (lane < 12) {
                int j = 18 * 32 + lane;
                acc += x2[j] * wrow[j];
            }
            acc = warp_sum(acc);
            if (lane == 0) y10[k] = lrelu(acc + fc1b[k]);
        }
        __syncthreads();

        // fc2: [10]->[128]
        if (tid < 128) {
            float acc = fc2b[tid];
#pragma unroll
            for (int j = 0; j < 10; j++) acc += y10[j] * fc2w[tid * 10 + j];
            y128[tid] = lrelu(acc);
        }
        __syncthreads();

        // fc3 split: 32 rows/block, 4 rows/warp, all 4 in flight
        {
            float4 a4 = ((const float4*)y128)[lane];
            int kb = bid * 32 + warp * 4;
            float acc[4];
#pragma unroll
            for (int q = 0; q < 4; q++) {
                float4 w4 = *((const float4*)(fc3w + (kb + q) * 128) + lane);
                acc[q] = w4.x * a4.x + w4.y * a4.y + w4.z * a4.z + w4.w * a4.w;
            }
#pragma unroll
            for (int q = 0; q < 4; q++) acc[q] = warp_sum(acc[q]);
            if (lane == 0) {
#pragma unroll
                for (int q = 0; q < 4; q++)
                    g_act3[kb + q] = lrelu(acc[q] + fc3b[kb + q]);
            }
        }
    }
    cluster_sync_gmem();   // g_act3 complete across cluster

    // ---------- Phase C: fc4 split — 64 rows/block, 8 rows/warp ----------
    {
        const float4* ga3 = (const float4*)g_act3;
        float4 A0 = ga3[lane], A1 = ga3[lane + 32];
        int rb = bid * 64 + warp * 8;
        float acc[8];
#pragma unroll
        for (int q = 0; q < 8; q++) {
            const float4* wr = (const float4*)(fc4w + (rb + q) * 256);
            float4 w0 = wr[lane], w1 = wr[lane + 32];
            acc[q] = w0.x * A0.x + w0.y * A0.y + w0.z * A0.z + w0.w * A0.w
                   + w1.x * A1.x + w1.y * A1.y + w1.z * A1.z + w1.w * A1.w;
        }
#pragma unroll
        for (int q = 0; q < 8; q++) acc[q] = warp_sum(acc[q]);
        if (lane == 0) {
#pragma unroll
            for (int q = 0; q < 8; q++)
                g_act4[rb + q] = lrelu(acc[q] + fc4b[rb + q]);
        }
    }
    pdl_launch();
}

// ================= K2: fc5 [512]->[1024], warp-per-row =================
__global__ void __launch_bounds__(256, 1) k_fc5(
    const float* __restrict__ w, const float* __restrict__ b)
{
    int gw   = blockIdx.x * 8 + (threadIdx.x >> 5);   // 0..1023
    int lane = threadIdx.x & 31;
    const float4* wr = (const float4*)(w + gw * 512);
    float4 W[4];
#pragma unroll
    for (int it = 0; it < 4; it++) W[it] = wr[lane + 32 * it];
    float bb = b[gw];

    pdl_wait();   // g_act4 ready

    const float4* ar = (const float4*)g_act4;
    float acc = 0.f;
#pragma unroll
    for (int it = 0; it < 4; it++) {
        float4 a4 = ar[lane + 32 * it];
        acc += W[it].x * a4.x + W[it].y * a4.y + W[it].z * a4.z + W[it].w * a4.w;
    }
    acc = warp_sum(acc);
    if (lane == 0) g_act5[gw] = lrelu(acc + bb);
    pdl_launch();
}

// ================= K3: fc6 [1024]->[1764], warp-per-row =================
__global__ void __launch_bounds__(256, 1) k_fc6(
    const float* __restrict__ w, const float* __restrict__ b,
    float* __restrict__ out)
{
    int gw   = blockIdx.x * 8 + (threadIdx.x >> 5);   // 0..1767
    int lane = threadIdx.x & 31;
    bool valid = (gw < 1764);
    int gwc = valid ? gw : 0;

    const float4* wr = (const float4*)(w + (size_t)gwc * 1024);
    float4 W[8];
#pragma unroll
    for (int it = 0; it < 8; it++) W[it] = wr[lane + 32 * it];
    float bb = b[gwc];

    pdl_wait();   // g_act5 ready (uniform across block)

    const float4* ar = (const float4*)g_act5;
    float acc = 0.f;
#pragma unroll
    for (int it = 0; it < 8; it++) {
        float4 a4 = ar[lane + 32 * it];
        acc += W[it].x * a4.x + W[it].y * a4.y + W[it].z * a4.z + W[it].w * a4.w;
    }
    acc = warp_sum(acc);
    if (lane == 0 && valid) out[gw] = acc + bb;
}

// -------- host-side launch helper: PDL + optional cluster --------
template <typename... Args>
static void launch_pdl(void (*kern)(Args...), dim3 grid, dim3 blk, int cluster,
                       Args... args) {
    cudaLaunchConfig_t cfg = {};
    cfg.gridDim = grid;
    cfg.blockDim = blk;
    cfg.dynamicSmemBytes = 0;
    cfg.stream = 0;
    cudaLaunchAttribute attrs[2];
    int n = 0;
    attrs[n].id = cudaLaunchAttributeProgrammaticStreamSerialization;
    attrs[n].val.programmaticStreamSerializationAllowed = 1;
    n++;
    if (cluster > 0) {
        attrs[n].id = cudaLaunchAttributeClusterDimension;
        attrs[n].val.clusterDim.x = cluster;
        attrs[n].val.clusterDim.y = 1;
        attrs[n].val.clusterDim.z = 1;
        n++;
    }
    cfg.attrs = attrs;
    cfg.numAttrs = n;
    cudaLaunchKernelEx(&cfg, kern, args...);
}

extern "C" void kernel_launch(void* const* d_in, const int* in_sizes, int n_in,
                              void* d_out, int out_size) {
    // metadata order:
    // 0 features, 1 src, 2 dst (unused: dst[e] == e/32 by construction),
    // 3 theta1_w, 4 theta1_b, 5 phi1_w, 6 phi1_b,
    // 7 theta2_w, 8 theta2_b, 9 phi2_w, 10 phi2_b,
    // 11 fc1_w, 12 fc1_b, 13 fc2_w, 14 fc2_b, 15 fc3_w, 16 fc3_b,
    // 17 fc4_w, 18 fc4_b, 19 fc5_w, 20 fc5_b, 21 fc6_w, 22 fc6_b
    launch_pdl(k_head, dim3(CLU), dim3(256), CLU,
        (const float*)d_in[0], (const int*)d_in[1],
        (const float*)d_in[3], (const float*)d_in[4],
        (const float*)d_in[5], (const float*)d_in[6],
        (const float*)d_in[7], (const float*)d_in[8],
        (const float*)d_in[9], (const float*)d_in[10],
        (const float*)d_in[11], (const float*)d_in[12],
        (const float*)d_in[13], (const float*)d_in[14],
        (const float*)d_in[15], (const float*)d_in[16],
        (const float*)d_in[17], (const float*)d_in[18]);
    launch_pdl(k_fc5, dim3(128), dim3(256), 0,
        (const float*)d_in[19], (const float*)d_in[20]);
    launch_pdl(k_fc6, dim3(221), dim3(256), 0,
        (const float*)d_in[21], (const float*)d_in[22], (float*)d_out);
}